// round 13
// baseline (speedup 1.0000x reference)
#include <cuda_runtime.h>
#include <math.h>

#define T_STEPS 20
#define FULL 0xffffffffu

typedef unsigned long long ull;

__device__ __forceinline__ float tanhapx(float x) {
    float y;
    asm("tanh.approx.f32 %0, %1;" : "=f"(y) : "f"(x));
    return y;
}
__device__ __forceinline__ float sigapx(float x) {
    return fmaf(0.5f, tanhapx(0.5f * x), 0.5f);
}
__device__ __forceinline__ ull fma2(ull a, ull b, ull c) {
    ull d;
    asm("fma.rn.f32x2 %0, %1, %2, %3;" : "=l"(d) : "l"(a), "l"(b), "l"(c));
    return d;
}
__device__ __forceinline__ float2 upk(ull v) {
    float2 r;
    asm("mov.b64 {%0, %1}, %2;" : "=f"(r.x), "=f"(r.y) : "l"(v));
    return r;
}

__global__ __launch_bounds__(128, 1)
void controller_kernel(const float* __restrict__ w_ih,
                       const float* __restrict__ w_hh,
                       const float* __restrict__ b_ih,
                       const float* __restrict__ b_hh,
                       const float* __restrict__ g_emb,
                       const float* __restrict__ emb_kernel,
                       const float* __restrict__ emb_down,
                       const float* __restrict__ emb_up,
                       const float* __restrict__ w_kernel,
                       const float* __restrict__ w_down,
                       const float* __restrict__ w_up,
                       const float* __restrict__ noise,
                       float* __restrict__ out,
                       int out_size) {
    // Wx4[e][state] = {gate_i, gate_f, gate_g, gate_o} of
    //   (w_ih @ emb_e) + b_ih + b_hh
    // e: 0 = g_emb, 1..8 = kernel, 9..11 = down, 12..14 = up
    __shared__ __align__(16) float4 Wx4[15][32];
    __shared__ __align__(16) float embsh[15][32];
    __shared__ __align__(16) float hsh[2][32];   // double-buffered h
    __shared__ float gsh[160];                   // gumbels (mask+bias folded)
    __shared__ __align__(16) float projsh[3][8 * 36];
    __shared__ float logsh[T_STEPS][8];
    __shared__ int   ssh[T_STEPS];

    const int tid = threadIdx.x;

    // ================= init: all 128 threads =================
    {
        float wi[32];
        const float4* wi4 = (const float4*)w_ih;
#pragma unroll
        for (int i = 0; i < 8; ++i) {
            float4 q = wi4[tid * 8 + i];
            wi[4 * i + 0] = q.x; wi[4 * i + 1] = q.y;
            wi[4 * i + 2] = q.z; wi[4 * i + 3] = q.w;
        }
        const float bias = b_ih[tid] + b_hh[tid];

        for (int i = tid; i < 3 * 8 * 36; i += 128)
            ((float*)projsh)[i] = 0.0f;
        if (tid < 32) embsh[0][tid] = g_emb[tid];
        for (int i = tid; i < 8 * 32; i += 128)
            embsh[1 + (i >> 5)][i & 31] = emb_kernel[i];
        for (int i = tid; i < 3 * 32; i += 128) {
            embsh[9  + (i >> 5)][i & 31] = emb_down[i];
            embsh[12 + (i >> 5)][i & 31] = emb_up[i];
        }
        // gumbels, mask + positivity bias folded in:
        //  valid:   gumbel + 32 -> v in [~26, ~50]  (> 0)
        //  invalid: 8           -> v in [4.7, 11.3] (< valid min)
        for (int i = tid; i < T_STEPS * 8; i += 128) {
            const int tt = i >> 3, aa = i & 7;
            const bool valid = (tt < 14) || (aa < 3);
            float u = noise[i];
            gsh[i] = valid ? (32.0f - logf(-logf(u * (1.0f - 1e-6f) + 1e-7f)))
                           : 8.0f;
        }
        __syncthreads();

        for (int i = tid; i < 8 * 32; i += 128)
            projsh[0][(i >> 5) * 36 + (i & 31)] = w_kernel[i];
        for (int i = tid; i < 3 * 32; i += 128) {
            projsh[1][(i >> 5) * 36 + (i & 31)] = w_down[i];
            projsh[2][(i >> 5) * 36 + (i & 31)] = w_up[i];
        }

        // Wx, stored transposed: row tid = (gate tid>>5, state tid&31)
        float* const wxslot = ((float*)&Wx4[0][0])
                            + (tid & 31) * 4 + (tid >> 5);
#pragma unroll 5
        for (int e = 0; e < 15; ++e) {
            const float4* em4 = (const float4*)embsh[e];
            float a0 = bias, a1 = 0.0f, a2 = 0.0f, a3 = 0.0f;
#pragma unroll
            for (int i = 0; i < 8; ++i) {
                float4 v = em4[i];
                a0 = fmaf(wi[4 * i + 0], v.x, a0);
                a1 = fmaf(wi[4 * i + 1], v.y, a1);
                a2 = fmaf(wi[4 * i + 2], v.z, a2);
                a3 = fmaf(wi[4 * i + 3], v.w, a3);
            }
            wxslot[e * 128] = (a0 + a1) + (a2 + a3);
        }
    }
    __syncthreads();

    if (tid >= 32) return;   // single-warp recurrence from here

    const int j  = tid;
    const int a  = j & 7;
    const int sb = (j >> 3) * 8;

    // w_hh rows j,(j+32),(j+64),(j+96) as packed f32x2 pairs
    ull wgi2[16], wgf2[16], wgg2[16], wgo2[16];
    {
        const ulonglong2* wh2 = (const ulonglong2*)w_hh;   // 16B-aligned rows
#pragma unroll
        for (int i = 0; i < 8; ++i) {
            ulonglong2 v;
            v = wh2[j * 8 + i];
            wgi2[2 * i] = v.x; wgi2[2 * i + 1] = v.y;
            v = wh2[(j + 32) * 8 + i];
            wgf2[2 * i] = v.x; wgf2[2 * i + 1] = v.y;
            v = wh2[(j + 64) * 8 + i];
            wgg2[2 * i] = v.x; wgg2[2 * i + 1] = v.y;
            v = wh2[(j + 96) * 8 + i];
            wgo2[2 * i] = v.x; wgo2[2 * i + 1] = v.y;
        }
    }

    // phase-0 proj regs (packed)
    ull P0, P1, P2, P3;
    {
        const ulonglong2* prp = (const ulonglong2*)&projsh[0][a * 36 + sb];
        ulonglong2 v0 = prp[0], v1 = prp[1];
        P0 = v0.x; P1 = v0.y; P2 = v1.x; P3 = v1.y;
    }
    int ebase = 1;

    // prologue: h0 = 0, c0 = 0 -> gates = Wx[0]
    float c, h;
    {
        const float4 wx0 = Wx4[0][j];
        const float ai = sigapx(wx0.x);
        const float ag = tanhapx(wx0.z);
        const float ao = sigapx(wx0.w);
        c = ai * ag;                    // f-gate * c0 = 0
        h = ao * tanhapx(c);
    }

#pragma unroll 2
    for (int t = 0; t < T_STEPS; ++t) {
        if (t == 14 || t == 17) {
            const int phi = (t == 14) ? 1 : 2;
            ebase = (t == 14) ? 9 : 12;
            const ulonglong2* prp =
                (const ulonglong2*)&projsh[phi][a * 36 + sb];
            ulonglong2 v0 = prp[0], v1 = prp[1];
            P0 = v0.x; P1 = v0.y; P2 = v1.x; P3 = v1.y;
        }
        const int p = t & 1;
        const float gl = gsh[t * 8 + a];

        hsh[p][j] = h;
        __syncwarp();

        // ---- logits: packed dot over lane's 8-segment ----
        const ulonglong2 qv0 = *(const ulonglong2*)&hsh[p][sb];
        const ulonglong2 qv1 = *(const ulonglong2*)&hsh[p][sb + 4];
        ull acc0 = fma2(P0, qv0.x, 0ull);
        ull acc1 = fma2(P1, qv0.y, 0ull);
        acc0 = fma2(P2, qv1.x, acc0);
        acc1 = fma2(P3, qv1.y, acc1);
        const float2 u0 = upk(acc0), u1 = upk(acc1);
        float part = (u0.x + u0.y) + (u1.x + u1.y);
        part += __shfl_xor_sync(FULL, part, 8);
        part += __shfl_xor_sync(FULL, part, 16);

        // ---- 4-gate packed matvec (fills shfl/redux latency) ----
        ull ai0 = 0, ai1 = 0, af0 = 0, af1 = 0;
        ull ag0 = 0, ag1 = 0, ao0 = 0, ao1 = 0;
        const ulonglong2* h8 = (const ulonglong2*)hsh[p];
#pragma unroll
        for (int i = 0; i < 8; ++i) {
            const ulonglong2 hv = h8[i];
            ai0 = fma2(wgi2[2 * i],     hv.x, ai0);
            ai1 = fma2(wgi2[2 * i + 1], hv.y, ai1);
            af0 = fma2(wgf2[2 * i],     hv.x, af0);
            af1 = fma2(wgf2[2 * i + 1], hv.y, af1);
            ag0 = fma2(wgg2[2 * i],     hv.x, ag0);
            ag1 = fma2(wgg2[2 * i + 1], hv.y, ag1);
            ao0 = fma2(wgo2[2 * i],     hv.x, ao0);
            ao1 = fma2(wgo2[2 * i + 1], hv.y, ao1);
        }
        const float2 fi0 = upk(ai0), fi1 = upk(ai1);
        const float2 ff0 = upk(af0), ff1 = upk(af1);
        const float2 fg0 = upk(ag0), fg1 = upk(ag1);
        const float2 fo0 = upk(ao0), fo1 = upk(ao1);
        const float ghi = (fi0.x + fi0.y) + (fi1.x + fi1.y);
        const float ghf = (ff0.x + ff0.y) + (ff1.x + ff1.y);
        const float ghg = (fg0.x + fg0.y) + (fg1.x + fg1.y);
        const float gho = (fo0.x + fo0.y) + (fo1.x + fo1.y);

        // ---- Gumbel-argmax: positive v -> uint bits ordered ----
        const unsigned key = (__float_as_uint(part + gl) & ~7u)
                           | (unsigned)(7 - a);
        unsigned km;
        asm("redux.sync.max.u32 %0, %1, 0xffffffff;" : "=r"(km) : "r"(key));
        const int s = (int)((km & 7u) ^ 7u);

        if (j < 8) {
            logsh[t][j] = part;
            if (j == 0) ssh[t] = s;
        }

        // ---- next-state update: one LDS.128 Wx candidate fetch ----
        if (t < T_STEPS - 1) {
            const float4 wx = Wx4[ebase + s][j];
            const float ai = sigapx(ghi + wx.x);
            const float af = sigapx(ghf + wx.y);
            const float ag = tanhapx(ghg + wx.z);
            const float ao = sigapx(gho + wx.w);
            c = fmaf(af, c, ai * ag);
            h = ao * tanhapx(c);
        }
    }

    // ================= deferred stats (warp 0) =================
    __syncwarp();
    float lp = 0.0f, ent = 0.0f;
    if (j < T_STEPS) {
        const int s = ssh[j];
        const int nvalid = (j < 14) ? 8 : 3;
        float se = 0.0f, ss1 = 0.0f;
#pragma unroll
        for (int k = 0; k < 8; ++k) {
            if (k < nvalid) {
                const float l = logsh[j][k];
                const float e = __expf(l);
                se  += e;
                ss1 += e * l;
            }
        }
        const float lse = __logf(se);
        lp  = logsh[j][s] - lse;
        ent = lse - __fdividef(ss1, se);
        out[2 + j] = (float)s;
    }
#pragma unroll
    for (int o = 16; o > 0; o >>= 1) {
        lp  += __shfl_xor_sync(FULL, lp,  o);
        ent += __shfl_xor_sync(FULL, ent, o);
    }
    if (j == 0) {
        out[0] = lp;
        out[1] = ent;
    }
}

extern "C" void kernel_launch(void* const* d_in, const int* in_sizes, int n_in,
                              void* d_out, int out_size) {
    const float* w_ih       = (const float*)d_in[0];
    const float* w_hh       = (const float*)d_in[1];
    const float* b_ih       = (const float*)d_in[2];
    const float* b_hh       = (const float*)d_in[3];
    const float* g_emb      = (const float*)d_in[4];
    const float* emb_kernel = (const float*)d_in[5];
    const float* emb_down   = (const float*)d_in[6];
    const float* emb_up     = (const float*)d_in[7];
    const float* w_kernel   = (const float*)d_in[8];
    const float* w_down     = (const float*)d_in[9];
    const float* w_up       = (const float*)d_in[10];
    const float* noise      = (const float*)d_in[11];
    float* out = (float*)d_out;

    controller_kernel<<<1, 128>>>(w_ih, w_hh, b_ih, b_hh, g_emb,
                                  emb_kernel, emb_down, emb_up,
                                  w_kernel, w_down, w_up, noise,
                                  out, out_size);
}